// round 2
// baseline (speedup 1.0000x reference)
#include <cuda_runtime.h>
#include <math.h>
#include <stdint.h>

// Model constants
#define BH      8      // heads
#define HDIM    64     // head dim
#define DMODEL  512
#define SENC    2048
#define NB_ENC  2
#define SRTR    72
#define NB_RTR  64
#define NTOK_ENC 4096
#define NTOK_RTR 4608
#define FFH     1024

// Scratch layout (floats)
#define T1        2359296ull          // 4608*512
#define OFF_XN    0ull
#define OFF_QKV   2359296ull          // 4608*1536 = 7077888
#define OFF_Q     9437184ull
#define OFF_K     11796480ull
#define OFF_V     14155776ull
#define OFF_ATT   16515072ull
#define OFF_H     18874368ull         // 4608*2048 = 9437184
#define OFF_ACT   28311552ull         // 4608*1024 = 4718592
#define OFF_X     33030144ull
#define OFF_XR    35389440ull
#define OFF_ROWS  37748736ull         // 512*512
#define OFF_OUT   38010880ull         // 512*256
#define OFF_KNR   38141952ull         // 512
#define OFF_KNG   38142464ull
#define OFF_RL    38142976ull         // 32*64*16
#define OFF_GL    38175744ull
#define SCRATCH_FLOATS 38208512ull

__device__ float g_s[SCRATCH_FLOATS];

// ---------------- helpers ----------------
__device__ __forceinline__ float bsum128(float v, volatile float* red) {
    int tid = threadIdx.x;
    red[tid] = v;
    for (int off = 64; off >= 1; off >>= 1) {
        __syncthreads();
        if (tid < off) red[tid] += red[tid + off];
    }
    __syncthreads();
    float r = red[0];
    __syncthreads();
    return r;
}

__device__ __forceinline__ float bmax128(float v, volatile float* red) {
    int tid = threadIdx.x;
    red[tid] = v;
    for (int off = 64; off >= 1; off >>= 1) {
        __syncthreads();
        if (tid < off) red[tid] = fmaxf(red[tid], red[tid + off]);
    }
    __syncthreads();
    float r = red[0];
    __syncthreads();
    return r;
}

// ---------------- kernels ----------------
__global__ void copy_k(const float* __restrict__ src, float* __restrict__ dst, int n) {
    int i = blockIdx.x * blockDim.x + threadIdx.x;
    if (i < n) dst[i] = src[i];
}

// One block (128 thr) per token row of 512
__global__ void rmsnorm_k(const float* __restrict__ x, const float* __restrict__ w,
                          float* __restrict__ y) {
    __shared__ float red[128];
    size_t row = (size_t)blockIdx.x * DMODEL;
    int tid = threadIdx.x;
    float ss = 0.f;
    for (int i = tid; i < DMODEL; i += 128) {
        float v = x[row + i];
        ss += v * v;
    }
    float tot = bsum128(ss, red);
    float scale = rsqrtf(tot / (float)DMODEL + 1e-6f);
    for (int i = tid; i < DMODEL; i += 128)
        y[row + i] = x[row + i] * scale * w[i];
}

// C[M,N] = (accum? C : 0) + A[M,K] @ B[K,N]. M,N mult of 64; K mult of 16.
__global__ __launch_bounds__(256) void sgemm_k(const float* __restrict__ A,
                                               const float* __restrict__ Bm,
                                               float* __restrict__ C,
                                               int M, int N, int K, int accum) {
    __shared__ float As[16][65];
    __shared__ float Bs[16][64];
    int bm = blockIdx.y * 64, bn = blockIdx.x * 64;
    int tx = threadIdx.x, ty = threadIdx.y;
    int tid = ty * 16 + tx;
    float acc[4][4];
#pragma unroll
    for (int i = 0; i < 4; i++)
#pragma unroll
        for (int j = 0; j < 4; j++) acc[i][j] = 0.f;

    for (int k0 = 0; k0 < K; k0 += 16) {
        for (int i = tid; i < 64 * 16; i += 256) {
            int m = i >> 4, kk = i & 15;
            As[kk][m] = A[(size_t)(bm + m) * K + k0 + kk];
        }
        for (int i = tid; i < 16 * 64; i += 256) {
            int kk = i >> 6, n = i & 63;
            Bs[kk][n] = Bm[(size_t)(k0 + kk) * N + bn + n];
        }
        __syncthreads();
#pragma unroll
        for (int kk = 0; kk < 16; kk++) {
            float a[4], b[4];
#pragma unroll
            for (int i = 0; i < 4; i++) a[i] = As[kk][ty + 16 * i];
#pragma unroll
            for (int j = 0; j < 4; j++) b[j] = Bs[kk][tx + 16 * j];
#pragma unroll
            for (int i = 0; i < 4; i++)
#pragma unroll
                for (int j = 0; j < 4; j++) acc[i][j] += a[i] * b[j];
        }
        __syncthreads();
    }
#pragma unroll
    for (int i = 0; i < 4; i++)
#pragma unroll
        for (int j = 0; j < 4; j++) {
            size_t ci = (size_t)(bm + ty + 16 * i) * N + bn + tx + 16 * j;
            if (accum) C[ci] += acc[i][j];
            else       C[ci] = acc[i][j];
        }
}

// qkv row -> q/k (RoPE) and v, layout [bh][SEQ][64]. grid=ntok, block=256
__global__ void split_rope_k(const float* __restrict__ qkv,
                             float* __restrict__ Q, float* __restrict__ K,
                             float* __restrict__ V, int SEQ) {
    int tok = blockIdx.x;
    int b = tok / SEQ, s = tok % SEQ;
    const float* row = qkv + (size_t)tok * 1536;
    int tid = threadIdx.x;               // 0..255
    int h = tid >> 5, i = tid & 31;      // head, rotation-pair index
    float q1 = row[h * 64 + i], q2 = row[h * 64 + i + 32];
    float k1 = row[512 + h * 64 + i], k2 = row[512 + h * 64 + i + 32];
    float inv = powf(1e-4f, (float)i * (1.0f / 32.0f));
    float ang = (float)s * inv;
    float c = cosf(ang), sn = sinf(ang);
    size_t base = ((size_t)(b * BH + h) * SEQ + s) * 64;
    Q[base + i]      =  q1 * c + q2 * sn;
    Q[base + i + 32] = -q1 * sn + q2 * c;
    K[base + i]      =  k1 * c + k2 * sn;
    K[base + i + 32] = -k1 * sn + k2 * c;
    for (int j = tid; j < 512; j += 256) {
        int hh = j >> 6, dd = j & 63;
        V[((size_t)(b * BH + hh) * SEQ + s) * 64 + dd] = row[1024 + j];
    }
}

// One block (128 thr) per (query, bh). Scores staged in smem, exact softmax.
// O is [ntok, 512] concat-head layout. maskmode 1: block-causal + doc match.
__global__ __launch_bounds__(128) void attn_k(const float* __restrict__ Q,
                                              const float* __restrict__ K,
                                              const float* __restrict__ V,
                                              float* __restrict__ O,
                                              const int* __restrict__ doc,
                                              int SEQ, int maskmode) {
    __shared__ float sq[64];
    __shared__ float sp[2048];
    __shared__ float red[128];
    int q = blockIdx.x;
    int bh = blockIdx.y;
    int b = bh / BH, h = bh % BH;
    int tid = threadIdx.x;
    const float* Qr = Q + ((size_t)bh * SEQ + q) * 64;
    if (tid < 64) sq[tid] = Qr[tid];
    __syncthreads();

    int kend = SEQ;
    int mydoc = 0;
    if (maskmode == 1) {
        kend = ((q >> 6) + 1) << 6;
        mydoc = doc[b * SEQ + q];
    }
    float m = -1e30f;
    for (int k = tid; k < kend; k += 128) {
        float s = -1e30f;
        bool ok = (maskmode == 0) || (doc[b * SEQ + k] == mydoc);
        if (ok) {
            const float4* kr = (const float4*)(K + ((size_t)bh * SEQ + k) * 64);
            const float4* qr = (const float4*)sq;
            float a = 0.f;
#pragma unroll
            for (int i = 0; i < 16; i++) {
                float4 kv = kr[i], qv = qr[i];
                a += kv.x * qv.x + kv.y * qv.y + kv.z * qv.z + kv.w * qv.w;
            }
            s = a * 0.125f;
        }
        sp[k] = s;
        m = fmaxf(m, s);
    }
    m = bmax128(m, red);

    float l = 0.f;
    for (int k = tid; k < kend; k += 128) {
        float e = expf(sp[k] - m);
        sp[k] = e;
        l += e;
    }
    l = bsum128(l, red);

    int d = tid & 63, half = tid >> 6;
    float acc = 0.f;
    for (int k = half; k < kend; k += 2)
        acc += sp[k] * V[((size_t)bh * SEQ + k) * 64 + d];
    red[tid] = acc;
    __syncthreads();
    if (tid < 64) {
        float o = (red[tid] + red[tid + 64]) / l;
        O[(size_t)(b * SEQ + q) * DMODEL + h * 64 + tid] = o;
    }
}

__global__ void silu_k(const float* __restrict__ hbuf, float* __restrict__ act, int n) {
    int i = blockIdx.x * blockDim.x + threadIdx.x;
    if (i >= n) return;
    int t = i >> 10, j = i & 1023;
    float a = hbuf[(size_t)t * 2048 + j];
    float b = hbuf[(size_t)t * 2048 + 1024 + j];
    act[i] = (a / (1.0f + expf(-a))) * b;
}

__global__ void build_xr_k(const float* __restrict__ x, const float* __restrict__ rt,
                           float* __restrict__ xr) {
    int i = blockIdx.x * blockDim.x + threadIdx.x;
    if (i >= NTOK_RTR * DMODEL) return;
    int blk = i / (SRTR * DMODEL);
    int rem = i % (SRTR * DMODEL);
    int t = rem / DMODEL, dd = rem % DMODEL;
    xr[i] = (t < 64) ? x[(size_t)(blk * 64 + t) * DMODEL + dd]
                     : rt[(size_t)(t - 64) * DMODEL + dd];
}

__global__ void gather_rows_k(const float* __restrict__ xr, float* __restrict__ rows) {
    int i = blockIdx.x * blockDim.x + threadIdx.x;
    if (i >= 512 * DMODEL) return;
    int row = i / DMODEL, dd = i % DMODEL;
    int blk = row >> 3, r = row & 7;
    rows[i] = xr[((size_t)blk * SRTR + 64 + r) * DMODEL + dd];
}

// norms of key columns (over DR dim). 1 block, 1024 threads.
__global__ void knorm_k(const float* __restrict__ kr, const float* __restrict__ kg,
                        float* __restrict__ knr, float* __restrict__ kng) {
    int tid = threadIdx.x;
    int which = tid >> 9;          // 0: router, 1: gate
    int idx = tid & 511;           // g*16 + e
    int g = idx >> 4, e = idx & 15;
    const float* src = which ? kg : kr;
    const float* col = src + (size_t)g * 128 * 16 + e;
    float s = 0.f;
    for (int d = 0; d < 128; d++) { float v = col[d * 16]; s += v * v; }
    float n = fmaxf(sqrtf(s), 1e-12f);
    if (which) kng[idx] = n; else knr[idx] = n;
}

// expand + l2norm + logits. grid = 32*64 blocks, 128 thr.
__global__ void logits_k(const float* __restrict__ outp,
                         const float* __restrict__ keys_r, const float* __restrict__ keys_g,
                         const float* __restrict__ knr, const float* __restrict__ kng,
                         float* __restrict__ rl, float* __restrict__ gl) {
    __shared__ float vr[128], vg[128], red[128];
    int g = blockIdx.x >> 6, bb = blockIdx.x & 63;
    int b = bb >> 5, l = bb & 31;
    int srcl = (l + 31) & 31;
    int r = g >> 2;
    const float* row = outp + (size_t)((b * 32 + srcl) * 8 + r) * 256;
    int tid = threadIdx.x;
    vr[tid] = row[tid];
    vg[tid] = row[128 + tid];
    float nr2 = bsum128(vr[tid] * vr[tid], red);
    float ng2 = bsum128(vg[tid] * vg[tid], red);
    float inr = 1.0f / fmaxf(sqrtf(nr2), 1e-12f);
    float ing = 1.0f / fmaxf(sqrtf(ng2), 1e-12f);
    if (tid < 16) {
        int e = tid;
        const float* kr = keys_r + (size_t)g * 128 * 16 + e;
        const float* kg = keys_g + (size_t)g * 128 * 16 + e;
        float dr = 0.f, dg = 0.f;
        for (int dd = 0; dd < 128; dd++) {
            dr += vr[dd] * kr[dd * 16];
            dg += vg[dd] * kg[dd * 16];
        }
        rl[(size_t)(g * 64 + bb) * 16 + e] = dr * inr / knr[g * 16 + e];
        gl[(size_t)(g * 64 + bb) * 16 + e] = dg * ing / kng[g * 16 + e];
    }
}

__global__ void topk_k(const float* __restrict__ rl, const float* __restrict__ gl,
                       float* __restrict__ out) {
    int t = blockIdx.x * blockDim.x + threadIdx.x;  // 0..2047 = g*64+bb
    if (t >= 2048) return;
    const float* r = rl + (size_t)t * 16;
    const float* g = gl + (size_t)t * 16;
    int i1 = 0; float v1 = r[0];
    for (int e = 1; e < 16; e++) if (r[e] > v1) { v1 = r[e]; i1 = e; }
    int i2 = -1; float v2 = -1e30f;
    for (int e = 0; e < 16; e++) {
        if (e == i1) continue;
        if (r[e] > v2) { v2 = r[e]; i2 = e; }
    }
    out[(size_t)t * 2 + 0] = v1;
    out[(size_t)t * 2 + 1] = v2;
    out[4096 + (size_t)t * 2 + 0] = g[i1];
    out[4096 + (size_t)t * 2 + 1] = g[i2];
}

// ---------------- host orchestration ----------------
static void run_layer(float* cur, const float* qkvw, const float* ow,
                      const float* upw, const float* dw,
                      const float* n1, const float* n2,
                      int ntok, int NB, int SEQ, int maskmode, const int* doc,
                      float* sb) {
    float* xn  = sb + OFF_XN;
    float* qkv = sb + OFF_QKV;
    float* qb  = sb + OFF_Q;
    float* kb  = sb + OFF_K;
    float* vb  = sb + OFF_V;
    float* att = sb + OFF_ATT;
    float* hb  = sb + OFF_H;
    float* act = sb + OFF_ACT;
    dim3 t16(16, 16);

    rmsnorm_k<<<ntok, 128>>>(cur, n1, xn);
    sgemm_k<<<dim3(1536 / 64, ntok / 64), t16>>>(xn, qkvw, qkv, ntok, 1536, 512, 0);
    split_rope_k<<<ntok, 256>>>(qkv, qb, kb, vb, SEQ);
    attn_k<<<dim3(SEQ, NB * BH), 128>>>(qb, kb, vb, att, doc, SEQ, maskmode);
    sgemm_k<<<dim3(512 / 64, ntok / 64), t16>>>(att, ow, cur, ntok, 512, 512, 1);
    rmsnorm_k<<<ntok, 128>>>(cur, n2, xn);
    sgemm_k<<<dim3(2048 / 64, ntok / 64), t16>>>(xn, upw, hb, ntok, 2048, 512, 0);
    silu_k<<<(ntok * 1024 + 255) / 256, 256>>>(hb, act, ntok * 1024);
    sgemm_k<<<dim3(512 / 64, ntok / 64), t16>>>(act, dw, cur, ntok, 512, 1024, 1);
}

extern "C" void kernel_launch(void* const* d_in, const int* in_sizes, int n_in,
                              void* d_out, int out_size) {
    const float* x_in   = (const float*)d_in[0];
    const int*   doc    = (const int*)d_in[1];
    const float* rt     = (const float*)d_in[2];
    const float* out_w  = (const float*)d_in[3];
    const float* keys_r = (const float*)d_in[4];
    const float* keys_g = (const float*)d_in[5];
    const float* e_qkv  = (const float*)d_in[6];
    const float* e_o    = (const float*)d_in[7];
    const float* e_up   = (const float*)d_in[8];
    const float* e_dn   = (const float*)d_in[9];
    const float* e_n1   = (const float*)d_in[10];
    const float* e_n2   = (const float*)d_in[11];
    const float* r_qkv  = (const float*)d_in[12];
    const float* r_o    = (const float*)d_in[13];
    const float* r_up   = (const float*)d_in[14];
    const float* r_dn   = (const float*)d_in[15];
    const float* r_n1   = (const float*)d_in[16];
    const float* r_n2   = (const float*)d_in[17];
    float* out = (float*)d_out;

    float* sb;
    cudaGetSymbolAddress((void**)&sb, g_s);
    float* xbuf = sb + OFF_X;
    float* xr   = sb + OFF_XR;
    float* rows = sb + OFF_ROWS;
    float* outp = sb + OFF_OUT;
    float* knr  = sb + OFF_KNR;
    float* kng  = sb + OFF_KNG;
    float* rl   = sb + OFF_RL;
    float* gl   = sb + OFF_GL;

    // x -> scratch
    copy_k<<<(NTOK_ENC * DMODEL + 255) / 256, 256>>>(x_in, xbuf, NTOK_ENC * DMODEL);

    // 4 encoder layers (block-causal + doc mask)
    for (int i = 0; i < 4; i++) {
        run_layer(xbuf,
                  e_qkv + (size_t)i * 512 * 1536,
                  e_o   + (size_t)i * 512 * 512,
                  e_up  + (size_t)i * 512 * 2048,
                  e_dn  + (size_t)i * 1024 * 512,
                  e_n1  + (size_t)i * 512,
                  e_n2  + (size_t)i * 512,
                  NTOK_ENC, NB_ENC, SENC, 1, doc, sb);
    }

    // build router sequences: 64 blocks x (64 tokens + 8 router tokens)
    build_xr_k<<<(NTOK_RTR * DMODEL + 255) / 256, 256>>>(xbuf, rt, xr);

    // 2 router layers (full attention within 72 tokens)
    for (int i = 0; i < 2; i++) {
        run_layer(xr,
                  r_qkv + (size_t)i * 512 * 1536,
                  r_o   + (size_t)i * 512 * 512,
                  r_up  + (size_t)i * 512 * 2048,
                  r_dn  + (size_t)i * 1024 * 512,
                  r_n1  + (size_t)i * 512,
                  r_n2  + (size_t)i * 512,
                  NTOK_RTR, NB_RTR, SRTR, 0, nullptr, sb);
    }

    // router-token rows -> out projection
    gather_rows_k<<<(512 * DMODEL + 255) / 256, 256>>>(xr, rows);
    sgemm_k<<<dim3(256 / 64, 512 / 64), dim3(16, 16)>>>(rows, out_w, outp, 512, 256, 512, 0);

    // routed logits + top-k
    knorm_k<<<1, 1024>>>(keys_r, keys_g, knr, kng);
    logits_k<<<32 * 64, 128>>>(outp, keys_r, keys_g, knr, kng, rl, gl);
    topk_k<<<16, 128>>>(rl, gl, out);
}

// round 4
// speedup vs baseline: 1.3308x; 1.3308x over previous
#include <cuda_runtime.h>
#include <math.h>
#include <stdint.h>

// Model constants
#define BH      8      // heads
#define HDIM    64     // head dim
#define DMODEL  512
#define SENC    2048
#define NB_ENC  2
#define SRTR    72
#define NB_RTR  64
#define NTOK_ENC 4096
#define NTOK_RTR 4608
#define FFH     1024

// Scratch layout (floats)
#define OFF_XN    0ull
#define OFF_QKV   2359296ull
#define OFF_Q     9437184ull
#define OFF_K     11796480ull
#define OFF_V     14155776ull
#define OFF_ATT   16515072ull
#define OFF_H     18874368ull
#define OFF_ACT   28311552ull
#define OFF_X     33030144ull
#define OFF_XR    35389440ull
#define OFF_ROWS  37748736ull
#define OFF_OUT   38010880ull
#define OFF_KNR   38141952ull
#define OFF_KNG   38142464ull
#define OFF_RL    38142976ull
#define OFF_GL    38175744ull
#define SCRATCH_FLOATS 38208512ull

__device__ float g_s[SCRATCH_FLOATS];

// ---------------- helpers ----------------
__device__ __forceinline__ float bsum128(float v, volatile float* red) {
    int tid = threadIdx.x;
    red[tid] = v;
    for (int off = 64; off >= 1; off >>= 1) {
        __syncthreads();
        if (tid < off) red[tid] += red[tid + off];
    }
    __syncthreads();
    float r = red[0];
    __syncthreads();
    return r;
}

__device__ __forceinline__ float bmax128(float v, volatile float* red) {
    int tid = threadIdx.x;
    red[tid] = v;
    for (int off = 64; off >= 1; off >>= 1) {
        __syncthreads();
        if (tid < off) red[tid] = fmaxf(red[tid], red[tid + off]);
    }
    __syncthreads();
    float r = red[0];
    __syncthreads();
    return r;
}

__device__ __forceinline__ uint32_t tf32_of(float x) {
    uint32_t u;
    asm("cvt.rna.tf32.f32 %0, %1;" : "=r"(u) : "f"(x));
    return u;
}

// split v into tf32 hi + tf32 lo (hi+lo captures ~21 mantissa bits)
__device__ __forceinline__ void tf32_split(float v, uint32_t& hi, uint32_t& lo) {
    hi = tf32_of(v);
    lo = tf32_of(v - __uint_as_float(hi));
}

__device__ __forceinline__ void mma_tf32(float* c, const uint32_t* a, const uint32_t* b) {
    asm volatile(
        "mma.sync.aligned.m16n8k8.row.col.f32.tf32.tf32.f32 "
        "{%0,%1,%2,%3}, {%4,%5,%6,%7}, {%8,%9}, {%0,%1,%2,%3};"
        : "+f"(c[0]), "+f"(c[1]), "+f"(c[2]), "+f"(c[3])
        : "r"(a[0]), "r"(a[1]), "r"(a[2]), "r"(a[3]), "r"(b[0]), "r"(b[1]));
}

// ---------------- kernels ----------------
__global__ void copy_k(const float* __restrict__ src, float* __restrict__ dst, int n) {
    int i = blockIdx.x * blockDim.x + threadIdx.x;
    if (i < n) dst[i] = src[i];
}

__global__ void rmsnorm_k(const float* __restrict__ x, const float* __restrict__ w,
                          float* __restrict__ y) {
    __shared__ float red[128];
    size_t row = (size_t)blockIdx.x * DMODEL;
    int tid = threadIdx.x;
    float ss = 0.f;
    for (int i = tid; i < DMODEL; i += 128) {
        float v = x[row + i];
        ss += v * v;
    }
    float tot = bsum128(ss, red);
    float scale = rsqrtf(tot / (float)DMODEL + 1e-6f);
    for (int i = tid; i < DMODEL; i += 128)
        y[row + i] = x[row + i] * scale * w[i];
}

// ---- Tensor-core 3xTF32 GEMM (fp32-accurate) ----
// C[M,N] = (accum? C : 0) + A[M,K] @ B[K,N]
// M,N multiples of 128; K multiple of 16.
// Block 256 thr (8 warps, 2x4), tile 128x128, BK=16, double-buffered fp32 smem.
// Splitting to tf32 hi/lo happens at fragment-load time (3 MMAs per logical MMA).
#define ASTRIDE 20
#define BSTRIDE 136
__global__ __launch_bounds__(256) void sgemm_tc(const float* __restrict__ A,
                                                const float* __restrict__ Bm,
                                                float* __restrict__ C,
                                                int M, int N, int K, int accum) {
    __shared__ float As[2][128][ASTRIDE];
    __shared__ float Bs[2][16][BSTRIDE];
    int tid = threadIdx.x;
    int lane = tid & 31, warp = tid >> 5;
    int wm = warp >> 2, wn = warp & 3;      // 2 x 4 warp grid
    int grp = lane >> 2, qid = lane & 3;
    int bm = blockIdx.y * 128, bn = blockIdx.x * 128;

    float acc[4][4][4];
#pragma unroll
    for (int i = 0; i < 4; i++)
#pragma unroll
        for (int j = 0; j < 4; j++)
#pragma unroll
            for (int t = 0; t < 4; t++) acc[i][j][t] = 0.f;

    int ar = tid >> 2, ac = tid & 3;
    float4 pa[2], pb[2];

#define LOAD_A(k0)                                                              \
    {                                                                           \
        pa[0] = *(const float4*)(A + (size_t)(bm + ar) * K + (k0) + 4 * ac);    \
        pa[1] = *(const float4*)(A + (size_t)(bm + 64 + ar) * K + (k0) + 4 * ac); \
    }
#define LOAD_B(k0)                                                              \
    {                                                                           \
        int i0 = tid, i1 = tid + 256;                                           \
        pb[0] = *(const float4*)(Bm + (size_t)((k0) + (i0 >> 5)) * N + bn + 4 * (i0 & 31)); \
        pb[1] = *(const float4*)(Bm + (size_t)((k0) + (i1 >> 5)) * N + bn + 4 * (i1 & 31)); \
    }
#define STORE_AB(buf)                                                           \
    {                                                                           \
        *(float4*)&As[buf][ar][4 * ac] = pa[0];                                 \
        *(float4*)&As[buf][64 + ar][4 * ac] = pa[1];                            \
        int i0 = tid, i1 = tid + 256;                                           \
        *(float4*)&Bs[buf][i0 >> 5][4 * (i0 & 31)] = pb[0];                     \
        *(float4*)&Bs[buf][i1 >> 5][4 * (i1 & 31)] = pb[1];                     \
    }

    LOAD_A(0);
    LOAD_B(0);
    STORE_AB(0);
    __syncthreads();

    int nk = K >> 4;
    for (int kt = 0; kt < nk; kt++) {
        int buf = kt & 1;
        if (kt + 1 < nk) {
            LOAD_A((kt + 1) << 4);
            LOAD_B((kt + 1) << 4);
        }
#pragma unroll
        for (int kk = 0; kk < 16; kk += 8) {
            uint32_t ah[4][4], al[4][4], bh[4][2], bl[4][2];
#pragma unroll
            for (int mt = 0; mt < 4; mt++) {
                int r0 = wm * 64 + mt * 16 + grp;
                tf32_split(As[buf][r0][kk + qid],          ah[mt][0], al[mt][0]);
                tf32_split(As[buf][r0 + 8][kk + qid],      ah[mt][1], al[mt][1]);
                tf32_split(As[buf][r0][kk + qid + 4],      ah[mt][2], al[mt][2]);
                tf32_split(As[buf][r0 + 8][kk + qid + 4],  ah[mt][3], al[mt][3]);
            }
#pragma unroll
            for (int nt = 0; nt < 4; nt++) {
                int c0 = wn * 32 + nt * 8 + grp;
                tf32_split(Bs[buf][kk + qid][c0],     bh[nt][0], bl[nt][0]);
                tf32_split(Bs[buf][kk + qid + 4][c0], bh[nt][1], bl[nt][1]);
            }
#pragma unroll
            for (int mt = 0; mt < 4; mt++)
#pragma unroll
                for (int nt = 0; nt < 4; nt++) {
                    mma_tf32(acc[mt][nt], al[mt], bh[nt]);
                    mma_tf32(acc[mt][nt], ah[mt], bl[nt]);
                    mma_tf32(acc[mt][nt], ah[mt], bh[nt]);
                }
        }
        if (kt + 1 < nk) STORE_AB(buf ^ 1);
        __syncthreads();
    }

#pragma unroll
    for (int mt = 0; mt < 4; mt++) {
#pragma unroll
        for (int nt = 0; nt < 4; nt++) {
            int r0 = bm + wm * 64 + mt * 16 + grp;
            int c0 = bn + wn * 32 + nt * 8 + 2 * qid;
            size_t i00 = (size_t)r0 * N + c0;
            size_t i10 = (size_t)(r0 + 8) * N + c0;
            if (accum) {
                C[i00]     += acc[mt][nt][0];
                C[i00 + 1] += acc[mt][nt][1];
                C[i10]     += acc[mt][nt][2];
                C[i10 + 1] += acc[mt][nt][3];
            } else {
                C[i00]     = acc[mt][nt][0];
                C[i00 + 1] = acc[mt][nt][1];
                C[i10]     = acc[mt][nt][2];
                C[i10 + 1] = acc[mt][nt][3];
            }
        }
    }
#undef LOAD_A
#undef LOAD_B
#undef STORE_AB
}

// qkv row -> q/k (RoPE) and v, layout [bh][SEQ][64]. grid=ntok, block=256
__global__ void split_rope_k(const float* __restrict__ qkv,
                             float* __restrict__ Q, float* __restrict__ K,
                             float* __restrict__ V, int SEQ) {
    int tok = blockIdx.x;
    int b = tok / SEQ, s = tok % SEQ;
    const float* row = qkv + (size_t)tok * 1536;
    int tid = threadIdx.x;
    int h = tid >> 5, i = tid & 31;
    float q1 = row[h * 64 + i], q2 = row[h * 64 + i + 32];
    float k1 = row[512 + h * 64 + i], k2 = row[512 + h * 64 + i + 32];
    float inv = powf(1e-4f, (float)i * (1.0f / 32.0f));
    float ang = (float)s * inv;
    float c = cosf(ang), sn = sinf(ang);
    size_t base = ((size_t)(b * BH + h) * SEQ + s) * 64;
    Q[base + i]      =  q1 * c + q2 * sn;
    Q[base + i + 32] = -q1 * sn + q2 * c;
    K[base + i]      =  k1 * c + k2 * sn;
    K[base + i + 32] = -k1 * sn + k2 * c;
    for (int j = tid; j < 512; j += 256) {
        int hh = j >> 6, dd = j & 63;
        V[((size_t)(b * BH + hh) * SEQ + s) * 64 + dd] = row[1024 + j];
    }
}

// One block (128 thr) per (query, bh). Scores staged in smem, exact softmax.
__global__ __launch_bounds__(128) void attn_k(const float* __restrict__ Q,
                                              const float* __restrict__ K,
                                              const float* __restrict__ V,
                                              float* __restrict__ O,
                                              const int* __restrict__ doc,
                                              int SEQ, int maskmode) {
    __shared__ float sq[64];
    __shared__ float sp[2048];
    __shared__ float red[128];
    int q = blockIdx.x;
    int bh = blockIdx.y;
    int b = bh / BH, h = bh % BH;
    int tid = threadIdx.x;
    const float* Qr = Q + ((size_t)bh * SEQ + q) * 64;
    if (tid < 64) sq[tid] = Qr[tid];
    __syncthreads();

    int kend = SEQ;
    int mydoc = 0;
    if (maskmode == 1) {
        kend = ((q >> 6) + 1) << 6;
        mydoc = doc[b * SEQ + q];
    }
    float m = -1e30f;
    for (int k = tid; k < kend; k += 128) {
        float s = -1e30f;
        bool ok = (maskmode == 0) || (doc[b * SEQ + k] == mydoc);
        if (ok) {
            const float4* kr = (const float4*)(K + ((size_t)bh * SEQ + k) * 64);
            const float4* qr = (const float4*)sq;
            float a = 0.f;
#pragma unroll
            for (int i = 0; i < 16; i++) {
                float4 kv = kr[i], qv = qr[i];
                a += kv.x * qv.x + kv.y * qv.y + kv.z * qv.z + kv.w * qv.w;
            }
            s = a * 0.125f;
        }
        sp[k] = s;
        m = fmaxf(m, s);
    }
    m = bmax128(m, red);

    float l = 0.f;
    for (int k = tid; k < kend; k += 128) {
        float e = expf(sp[k] - m);
        sp[k] = e;
        l += e;
    }
    l = bsum128(l, red);

    int d = tid & 63, half = tid >> 6;
    float acc = 0.f;
    for (int k = half; k < kend; k += 2)
        acc += sp[k] * V[((size_t)bh * SEQ + k) * 64 + d];
    red[tid] = acc;
    __syncthreads();
    if (tid < 64) {
        float o = (red[tid] + red[tid + 64]) / l;
        O[(size_t)(b * SEQ + q) * DMODEL + h * 64 + tid] = o;
    }
}

__global__ void silu_k(const float* __restrict__ hbuf, float* __restrict__ act, int n) {
    int i = blockIdx.x * blockDim.x + threadIdx.x;
    if (i >= n) return;
    int t = i >> 10, j = i & 1023;
    float a = hbuf[(size_t)t * 2048 + j];
    float b = hbuf[(size_t)t * 2048 + 1024 + j];
    act[i] = (a / (1.0f + expf(-a))) * b;
}

__global__ void build_xr_k(const float* __restrict__ x, const float* __restrict__ rt,
                           float* __restrict__ xr) {
    int i = blockIdx.x * blockDim.x + threadIdx.x;
    if (i >= NTOK_RTR * DMODEL) return;
    int blk = i / (SRTR * DMODEL);
    int rem = i % (SRTR * DMODEL);
    int t = rem / DMODEL, dd = rem % DMODEL;
    xr[i] = (t < 64) ? x[(size_t)(blk * 64 + t) * DMODEL + dd]
                     : rt[(size_t)(t - 64) * DMODEL + dd];
}

__global__ void gather_rows_k(const float* __restrict__ xr, float* __restrict__ rows) {
    int i = blockIdx.x * blockDim.x + threadIdx.x;
    if (i >= 512 * DMODEL) return;
    int row = i / DMODEL, dd = i % DMODEL;
    int blk = row >> 3, r = row & 7;
    rows[i] = xr[((size_t)blk * SRTR + 64 + r) * DMODEL + dd];
}

__global__ void knorm_k(const float* __restrict__ kr, const float* __restrict__ kg,
                        float* __restrict__ knr, float* __restrict__ kng) {
    int tid = threadIdx.x;
    int which = tid >> 9;
    int idx = tid & 511;
    int g = idx >> 4, e = idx & 15;
    const float* src = which ? kg : kr;
    const float* col = src + (size_t)g * 128 * 16 + e;
    float s = 0.f;
    for (int d = 0; d < 128; d++) { float v = col[d * 16]; s += v * v; }
    float n = fmaxf(sqrtf(s), 1e-12f);
    if (which) kng[idx] = n; else knr[idx] = n;
}

__global__ void logits_k(const float* __restrict__ outp,
                         const float* __restrict__ keys_r, const float* __restrict__ keys_g,
                         const float* __restrict__ knr, const float* __restrict__ kng,
                         float* __restrict__ rl, float* __restrict__ gl) {
    __shared__ float vr[128], vg[128], red[128];
    int g = blockIdx.x >> 6, bb = blockIdx.x & 63;
    int b = bb >> 5, l = bb & 31;
    int srcl = (l + 31) & 31;
    int r = g >> 2;
    const float* row = outp + (size_t)((b * 32 + srcl) * 8 + r) * 256;
    int tid = threadIdx.x;
    vr[tid] = row[tid];
    vg[tid] = row[128 + tid];
    float nr2 = bsum128(vr[tid] * vr[tid], red);
    float ng2 = bsum128(vg[tid] * vg[tid], red);
    float inr = 1.0f / fmaxf(sqrtf(nr2), 1e-12f);
    float ing = 1.0f / fmaxf(sqrtf(ng2), 1e-12f);
    if (tid < 16) {
        int e = tid;
        const float* kr = keys_r + (size_t)g * 128 * 16 + e;
        const float* kg = keys_g + (size_t)g * 128 * 16 + e;
        float dr = 0.f, dg = 0.f;
        for (int dd = 0; dd < 128; dd++) {
            dr += vr[dd] * kr[dd * 16];
            dg += vg[dd] * kg[dd * 16];
        }
        rl[(size_t)(g * 64 + bb) * 16 + e] = dr * inr / knr[g * 16 + e];
        gl[(size_t)(g * 64 + bb) * 16 + e] = dg * ing / kng[g * 16 + e];
    }
}

__global__ void topk_k(const float* __restrict__ rl, const float* __restrict__ gl,
                       float* __restrict__ out) {
    int t = blockIdx.x * blockDim.x + threadIdx.x;
    if (t >= 2048) return;
    const float* r = rl + (size_t)t * 16;
    const float* g = gl + (size_t)t * 16;
    int i1 = 0; float v1 = r[0];
    for (int e = 1; e < 16; e++) if (r[e] > v1) { v1 = r[e]; i1 = e; }
    int i2 = -1; float v2 = -1e30f;
    for (int e = 0; e < 16; e++) {
        if (e == i1) continue;
        if (r[e] > v2) { v2 = r[e]; i2 = e; }
    }
    out[(size_t)t * 2 + 0] = v1;
    out[(size_t)t * 2 + 1] = v2;
    out[4096 + (size_t)t * 2 + 0] = g[i1];
    out[4096 + (size_t)t * 2 + 1] = g[i2];
}

// ---------------- host orchestration ----------------
static void run_layer(float* cur, const float* qkvw, const float* ow,
                      const float* upw, const float* dw,
                      const float* n1, const float* n2,
                      int ntok, int NB, int SEQ, int maskmode, const int* doc,
                      float* sb) {
    float* xn  = sb + OFF_XN;
    float* qkv = sb + OFF_QKV;
    float* qb  = sb + OFF_Q;
    float* kb  = sb + OFF_K;
    float* vb  = sb + OFF_V;
    float* att = sb + OFF_ATT;
    float* hb  = sb + OFF_H;
    float* act = sb + OFF_ACT;

    rmsnorm_k<<<ntok, 128>>>(cur, n1, xn);
    sgemm_tc<<<dim3(1536 / 128, ntok / 128), 256>>>(xn, qkvw, qkv, ntok, 1536, 512, 0);
    split_rope_k<<<ntok, 256>>>(qkv, qb, kb, vb, SEQ);
    attn_k<<<dim3(SEQ, NB * BH), 128>>>(qb, kb, vb, att, doc, SEQ, maskmode);
    sgemm_tc<<<dim3(512 / 128, ntok / 128), 256>>>(att, ow, cur, ntok, 512, 512, 1);
    rmsnorm_k<<<ntok, 128>>>(cur, n2, xn);
    sgemm_tc<<<dim3(2048 / 128, ntok / 128), 256>>>(xn, upw, hb, ntok, 2048, 512, 0);
    silu_k<<<(ntok * 1024 + 255) / 256, 256>>>(hb, act, ntok * 1024);
    sgemm_tc<<<dim3(512 / 128, ntok / 128), 256>>>(act, dw, cur, ntok, 512, 1024, 1);
}

extern "C" void kernel_launch(void* const* d_in, const int* in_sizes, int n_in,
                              void* d_out, int out_size) {
    const float* x_in   = (const float*)d_in[0];
    const int*   doc    = (const int*)d_in[1];
    const float* rt     = (const float*)d_in[2];
    const float* out_w  = (const float*)d_in[3];
    const float* keys_r = (const float*)d_in[4];
    const float* keys_g = (const float*)d_in[5];
    const float* e_qkv  = (const float*)d_in[6];
    const float* e_o    = (const float*)d_in[7];
    const float* e_up   = (const float*)d_in[8];
    const float* e_dn   = (const float*)d_in[9];
    const float* e_n1   = (const float*)d_in[10];
    const float* e_n2   = (const float*)d_in[11];
    const float* r_qkv  = (const float*)d_in[12];
    const float* r_o    = (const float*)d_in[13];
    const float* r_up   = (const float*)d_in[14];
    const float* r_dn   = (const float*)d_in[15];
    const float* r_n1   = (const float*)d_in[16];
    const float* r_n2   = (const float*)d_in[17];
    float* out = (float*)d_out;

    float* sb;
    cudaGetSymbolAddress((void**)&sb, g_s);
    float* xbuf = sb + OFF_X;
    float* xr   = sb + OFF_XR;
    float* rows = sb + OFF_ROWS;
    float* outp = sb + OFF_OUT;
    float* knr  = sb + OFF_KNR;
    float* kng  = sb + OFF_KNG;
    float* rl   = sb + OFF_RL;
    float* gl   = sb + OFF_GL;

    copy_k<<<(NTOK_ENC * DMODEL + 255) / 256, 256>>>(x_in, xbuf, NTOK_ENC * DMODEL);

    for (int i = 0; i < 4; i++) {
        run_layer(xbuf,
                  e_qkv + (size_t)i * 512 * 1536,
                  e_o   + (size_t)i * 512 * 512,
                  e_up  + (size_t)i * 512 * 2048,
                  e_dn  + (size_t)i * 1024 * 512,
                  e_n1  + (size_t)i * 512,
                  e_n2  + (size_t)i * 512,
                  NTOK_ENC, NB_ENC, SENC, 1, doc, sb);
    }

    build_xr_k<<<(NTOK_RTR * DMODEL + 255) / 256, 256>>>(xbuf, rt, xr);

    for (int i = 0; i < 2; i++) {
        run_layer(xr,
                  r_qkv + (size_t)i * 512 * 1536,
                  r_o   + (size_t)i * 512 * 512,
                  r_up  + (size_t)i * 512 * 2048,
                  r_dn  + (size_t)i * 1024 * 512,
                  r_n1  + (size_t)i * 512,
                  r_n2  + (size_t)i * 512,
                  NTOK_RTR, NB_RTR, SRTR, 0, nullptr, sb);
    }

    gather_rows_k<<<(512 * DMODEL + 255) / 256, 256>>>(xr, rows);
    sgemm_tc<<<dim3(256 / 128, 512 / 128), 256>>>(rows, out_w, outp, 512, 256, 512, 0);

    knorm_k<<<1, 1024>>>(keys_r, keys_g, knr, kng);
    logits_k<<<32 * 64, 128>>>(outp, keys_r, keys_g, knr, kng, rl, gl);
    topk_k<<<16, 128>>>(rl, gl, out);
}